// round 1
// baseline (speedup 1.0000x reference)
#include <cuda_runtime.h>

#define NB      4
#define GDIM    7
#define NREG    49      // 7*7
#define HH      224
#define CC      256
#define SS      1024
#define NQ      100
#define QT      64      // queries per CTA (2 q-tiles cover 100, padded)
#define CHUNK   32      // keys per chunk (== one image row-strip)
#define NCHUNK  32      // 1024/32
#define THREADS 512

#define KSTRIDE  260    // K  [CHUNK][KSTRIDE]  row-major keys (PV phase)
#define KTSTRIDE 33     // Kt [CC][KTSTRIDE]    transposed keys (QK phase)
#define QTSTRIDE 68     // Qt [CC][QTSTRIDE]    transposed queries
#define PSTRIDE  33     // P  [QT][PSTRIDE]     scores / probs

#define SMEM_FLOATS (CHUNK*KSTRIDE + CC*KTSTRIDE + CC*QTSTRIDE + QT*PSTRIDE + 3*QT)
#define SMEM_BYTES  (SMEM_FLOATS * 4)

#define OUT_ELEMS   (NB * NREG * NQ * CC)   // 5017600
#define POS_ELEMS   (NREG * 2)              // 98

// ---------------- packed f32x2 helpers ----------------
__device__ __forceinline__ unsigned long long pack2(float a, float b) {
    unsigned long long r;
    asm("mov.b64 %0, {%1, %2};" : "=l"(r) : "f"(a), "f"(b));
    return r;
}
__device__ __forceinline__ void unpack2(unsigned long long v, float& a, float& b) {
    asm("mov.b64 {%0, %1}, %2;" : "=f"(a), "=f"(b) : "l"(v));
}
__device__ __forceinline__ void fma2(unsigned long long& d,
                                     unsigned long long a, unsigned long long b) {
    asm("fma.rn.f32x2 %0, %1, %2, %0;" : "+l"(d) : "l"(a), "l"(b));
}
__device__ __forceinline__ void mul2(unsigned long long& d, unsigned long long a) {
    asm("mul.rn.f32x2 %0, %1, %0;" : "+l"(d) : "l"(a));
}

// ---------------- main fused attention kernel ----------------
// grid: 196 regions * 2 q-tiles = 392 CTAs, 512 threads
__global__ void __launch_bounds__(THREADS, 1)
attn_kernel(const float* __restrict__ images,
            const float* __restrict__ queries,
            float* __restrict__ out)
{
    extern __shared__ float smem[];
    float* sK  = smem;                       // [CHUNK][KSTRIDE]
    float* sKt = sK  + CHUNK * KSTRIDE;      // [CC][KTSTRIDE]
    float* sQt = sKt + CC * KTSTRIDE;        // [CC][QTSTRIDE]
    float* sP  = sQt + CC * QTSTRIDE;        // [QT][PSTRIDE]
    float* sM  = sP  + QT * PSTRIDE;         // [QT]
    float* sL  = sM  + QT;                   // [QT]
    float* sA  = sL  + QT;                   // [QT]

    const int bx     = blockIdx.x;
    const int region = bx >> 1;              // 0..195 = b*49 + n
    const int qtile  = bx & 1;
    const int b = region / NREG;
    const int n = region % NREG;
    const int gi = n / GDIM;
    const int gj = n % GDIM;

    const int tid  = threadIdx.x;
    const int lane = tid & 31;
    const int warp = tid >> 5;               // 0..15, owns q rows warp*4..warp*4+3

    // stage Q tile transposed: Qt[c][q]
    for (int id = tid; id < QT * CC; id += THREADS) {
        int q = id >> 8;          // 0..63
        int c = id & 255;
        int qg = qtile * QT + q;
        float v = (qg < NQ) ? queries[qg * CC + c] : 0.0f;
        sQt[c * QTSTRIDE + q] = v;
    }
    if (tid < QT) { sM[tid] = -3.0e38f; sL[tid] = 0.0f; }

    // O accumulators: 4 q rows x 8 channels (c = 4*lane + {0..3} and 128+4*lane+{0..3})
    unsigned long long acc[4][4];
    #pragma unroll
    for (int qq = 0; qq < 4; qq++)
        #pragma unroll
        for (int p = 0; p < 4; p++) acc[qq][p] = 0ull;

    __syncthreads();

    // region base: pixel (gi*32 + h, gj*32 + w); chunk ck == local row h=ck,
    // so each chunk is a CONTIGUOUS 32*256-float block of the image.
    const float* imgbase = images + ((size_t)(b * HH + gi * 32) * HH + gj * 32) * CC;

    for (int ck = 0; ck < NCHUNK; ck++) {
        // ---- load key chunk: 8192 contiguous floats -> K and Kt ----
        const float4* g = (const float4*)(imgbase + (size_t)ck * (HH * CC));
        #pragma unroll
        for (int it = 0; it < 4; it++) {
            int id = tid + it * THREADS;          // 0..2047
            int r  = id >> 6;                     // key row 0..31
            int c4 = id & 63;                     // float4 col
            float4 v = g[id];
            *(float4*)&sK[r * KSTRIDE + c4 * 4] = v;
            int c = c4 * 4;
            sKt[(c + 0) * KTSTRIDE + r] = v.x;
            sKt[(c + 1) * KTSTRIDE + r] = v.y;
            sKt[(c + 2) * KTSTRIDE + r] = v.z;
            sKt[(c + 3) * KTSTRIDE + r] = v.w;
        }
        __syncthreads();

        // ---- score phase: warp -> 4 q rows, lane -> key s=lane ----
        {
            unsigned long long sc01 = 0ull, sc23 = 0ull;
            #pragma unroll 8
            for (int c = 0; c < CC; c++) {
                const ulonglong2 qv = *(const ulonglong2*)&sQt[c * QTSTRIDE + warp * 4];
                float kv = sKt[c * KTSTRIDE + lane];
                unsigned long long kk = pack2(kv, kv);
                fma2(sc01, qv.x, kk);
                fma2(sc23, qv.y, kk);
            }
            float s0, s1, s2, s3;
            unpack2(sc01, s0, s1);
            unpack2(sc23, s2, s3);
            sP[(warp * 4 + 0) * PSTRIDE + lane] = s0;
            sP[(warp * 4 + 1) * PSTRIDE + lane] = s1;
            sP[(warp * 4 + 2) * PSTRIDE + lane] = s2;
            sP[(warp * 4 + 3) * PSTRIDE + lane] = s3;
        }
        __syncthreads();

        // ---- online softmax update (one thread per q row) ----
        if (tid < QT) {
            float mold = sM[tid];
            float* row = sP + tid * PSTRIDE;
            float mx = mold;
            #pragma unroll
            for (int s = 0; s < CHUNK; s++) mx = fmaxf(mx, row[s]);
            float alpha = __expf(mold - mx);   // 0 on first chunk
            float sum = 0.0f;
            #pragma unroll
            for (int s = 0; s < CHUNK; s++) {
                float p = __expf(row[s] - mx);
                row[s] = p;
                sum += p;
            }
            sL[tid] = sL[tid] * alpha + sum;
            sM[tid] = mx;
            sA[tid] = alpha;
        }
        __syncthreads();

        // ---- rescale accumulators, then accumulate P*V ----
        #pragma unroll
        for (int qq = 0; qq < 4; qq++) {
            float a = sA[warp * 4 + qq];
            unsigned long long aa = pack2(a, a);
            #pragma unroll
            for (int p = 0; p < 4; p++) mul2(acc[qq][p], aa);
        }
        #pragma unroll 4
        for (int s = 0; s < CHUNK; s++) {
            const ulonglong2 v0 = *(const ulonglong2*)&sK[s * KSTRIDE + lane * 4];
            const ulonglong2 v1 = *(const ulonglong2*)&sK[s * KSTRIDE + 128 + lane * 4];
            #pragma unroll
            for (int qq = 0; qq < 4; qq++) {
                float p = sP[(warp * 4 + qq) * PSTRIDE + s];
                unsigned long long pp = pack2(p, p);
                fma2(acc[qq][0], pp, v0.x);
                fma2(acc[qq][1], pp, v0.y);
                fma2(acc[qq][2], pp, v1.x);
                fma2(acc[qq][3], pp, v1.y);
            }
        }
        __syncthreads();
    }

    // ---- epilogue: normalize and store ----
    #pragma unroll
    for (int qq = 0; qq < 4; qq++) {
        int ql = warp * 4 + qq;
        int qg = qtile * QT + ql;
        if (qg >= NQ) continue;
        float inv = 1.0f / sL[ql];
        float r0, r1, r2, r3, r4, r5, r6, r7;
        unpack2(acc[qq][0], r0, r1);
        unpack2(acc[qq][1], r2, r3);
        unpack2(acc[qq][2], r4, r5);
        unpack2(acc[qq][3], r6, r7);
        float4 o0 = make_float4(r0 * inv, r1 * inv, r2 * inv, r3 * inv);
        float4 o1 = make_float4(r4 * inv, r5 * inv, r6 * inv, r7 * inv);
        size_t base = ((size_t)region * NQ + qg) * CC;
        *(float4*)&out[base + lane * 4]       = o0;
        *(float4*)&out[base + 128 + lane * 4] = o1;
    }
}

// ---------------- positions (second tuple output) ----------------
__global__ void pos_kernel(float* __restrict__ out, int out_size) {
    int t = threadIdx.x;
    if (t < NREG && out_size >= OUT_ELEMS + POS_ELEMS) {
        out[OUT_ELEMS + 2 * t + 0] = (float)(t / GDIM) * (1.0f / 7.0f);
        out[OUT_ELEMS + 2 * t + 1] = (float)(t % GDIM) * (1.0f / 7.0f);
    }
}

extern "C" void kernel_launch(void* const* d_in, const int* in_sizes, int n_in,
                              void* d_out, int out_size) {
    const float* images  = (const float*)d_in[0];
    const float* queries = (const float*)d_in[1];
    // defensive: metadata order should be (images, queries); swap if sizes say otherwise
    if (n_in >= 2 && in_sizes[0] == NQ * CC) {
        const float* t = images; images = queries; queries = t;
    }
    float* out = (float*)d_out;

    cudaFuncSetAttribute(attn_kernel,
                         cudaFuncAttributeMaxDynamicSharedMemorySize, SMEM_BYTES);

    attn_kernel<<<196 * 2, THREADS, SMEM_BYTES>>>(images, queries, out);
    pos_kernel<<<1, 64>>>(out, out_size);
}

// round 2
// speedup vs baseline: 1.2076x; 1.2076x over previous
#include <cuda_runtime.h>

#define NB      4
#define GDIM    7
#define NREG    49
#define HH      224
#define CC      256
#define NQ      100
#define ROWS    64      // q rows per CTA
#define RPW     8       // q rows per warp
#define THREADS 256
#define CHUNK   32      // keys per chunk (one image row-strip)
#define NCHUNK  32

#define KSTRIDE  260    // sK  [CHUNK][KSTRIDE]  row-major keys (PV)
#define KTSTRIDE 33     // sKt [CC][KTSTRIDE]    transposed keys (QK)
#define QTSTRIDE 68     // sQt [CC][QTSTRIDE]    transposed queries

#define SMEM_FLOATS (CHUNK*KSTRIDE + CC*KTSTRIDE + CC*QTSTRIDE)
#define SMEM_BYTES  (SMEM_FLOATS * 4)

#define OUT_ELEMS   (NB * NREG * NQ * CC)   // 5017600
#define POS_ELEMS   (NREG * 2)

// ---------------- packed f32x2 helpers ----------------
__device__ __forceinline__ unsigned long long pack2(float a, float b) {
    unsigned long long r;
    asm("mov.b64 %0, {%1, %2};" : "=l"(r) : "f"(a), "f"(b));
    return r;
}
__device__ __forceinline__ void unpack2(unsigned long long v, float& a, float& b) {
    asm("mov.b64 {%0, %1}, %2;" : "=f"(a), "=f"(b) : "l"(v));
}
__device__ __forceinline__ void fma2(unsigned long long& d,
                                     unsigned long long a, unsigned long long b) {
    asm("fma.rn.f32x2 %0, %1, %2, %0;" : "+l"(d) : "l"(a), "l"(b));
}
__device__ __forceinline__ void mul2(unsigned long long& d, unsigned long long a) {
    asm("mul.rn.f32x2 %0, %1, %0;" : "+l"(d) : "l"(a));
}

// ---------------- fused attention ----------------
// grid: 196 regions * 2 q-tiles = 392 CTAs, 256 threads (8 warps x 8 q-rows)
__global__ void __launch_bounds__(THREADS, 1)
attn_kernel(const float* __restrict__ images,
            const float* __restrict__ queries,
            float* __restrict__ out)
{
    extern __shared__ float smem[];
    float* sK  = smem;                       // [CHUNK][KSTRIDE]
    float* sKt = sK  + CHUNK * KSTRIDE;      // [CC][KTSTRIDE]
    float* sQt = sKt + CC * KTSTRIDE;        // [CC][QTSTRIDE]

    const int bx     = blockIdx.x;
    const int region = bx >> 1;
    const int qtile  = bx & 1;
    const int b  = region / NREG;
    const int n  = region % NREG;
    const int gi = n / GDIM;
    const int gj = n % GDIM;

    const int tid  = threadIdx.x;
    const int lane = tid & 31;
    const int warp = tid >> 5;               // 0..7, owns rows warp*8..warp*8+7

    // stage Q tile transposed: Qt[c][q]
    for (int id = tid; id < ROWS * CC; id += THREADS) {
        int q = id >> 8;
        int c = id & 255;
        int qg = qtile * ROWS + q;
        sQt[c * QTSTRIDE + q] = (qg < NQ) ? queries[qg * CC + c] : 0.0f;
    }

    // per-row online-softmax state in registers (identical across lanes of a warp)
    float m[RPW], l[RPW];
    #pragma unroll
    for (int r = 0; r < RPW; r++) { m[r] = -1e30f; l[r] = 0.0f; }

    // O accumulators: 8 rows x 8 channels (ch = 4*lane+{0..3}, 128+4*lane+{0..3})
    unsigned long long acc[RPW][4];
    #pragma unroll
    for (int r = 0; r < RPW; r++)
        #pragma unroll
        for (int j = 0; j < 4; j++) acc[r][j] = 0ull;

    const float* imgbase = images + ((size_t)(b * HH + gi * 32) * HH + gj * 32) * CC;

    // register prefetch of chunk 0 (32 keys = 8192 contiguous floats)
    float4 pf[8];
    {
        const float4* g = (const float4*)imgbase;
        #pragma unroll
        for (int it = 0; it < 8; it++) pf[it] = g[tid + it * THREADS];
    }

    for (int ck = 0; ck < NCHUNK; ck++) {
        __syncthreads();   // previous chunk's compute done (also orders Qt staging on ck=0)

        // deposit prefetched chunk into both smem layouts
        #pragma unroll
        for (int it = 0; it < 8; it++) {
            int id = tid + it * THREADS;      // 0..2047
            int r  = id >> 6;                 // key row 0..31
            int c4 = id & 63;                 // float4 col
            float4 v = pf[it];
            *(float4*)&sK[r * KSTRIDE + c4 * 4] = v;
            int c = c4 * 4;
            sKt[(c + 0) * KTSTRIDE + r] = v.x;
            sKt[(c + 1) * KTSTRIDE + r] = v.y;
            sKt[(c + 2) * KTSTRIDE + r] = v.z;
            sKt[(c + 3) * KTSTRIDE + r] = v.w;
        }
        __syncthreads();   // chunk visible to all warps

        // prefetch next chunk (latency hidden under compute below)
        if (ck + 1 < NCHUNK) {
            const float4* g = (const float4*)(imgbase + (size_t)(ck + 1) * (HH * CC));
            #pragma unroll
            for (int it = 0; it < 8; it++) pf[it] = g[tid + it * THREADS];
        }

        // ---- scores: 8 rows (row-pairs) x key=lane ----
        unsigned long long sc[4] = {0ull, 0ull, 0ull, 0ull};
        const float* qbase = sQt + warp * RPW;
        #pragma unroll 8
        for (int c = 0; c < CC; c++) {
            const ulonglong2 qv0 = *(const ulonglong2*)&qbase[c * QTSTRIDE];
            const ulonglong2 qv1 = *(const ulonglong2*)&qbase[c * QTSTRIDE + 4];
            float kv = sKt[c * KTSTRIDE + lane];
            unsigned long long kk = pack2(kv, kv);
            fma2(sc[0], qv0.x, kk);
            fma2(sc[1], qv0.y, kk);
            fma2(sc[2], qv1.x, kk);
            fma2(sc[3], qv1.y, kk);
        }
        float s[RPW];
        unpack2(sc[0], s[0], s[1]);
        unpack2(sc[1], s[2], s[3]);
        unpack2(sc[2], s[4], s[5]);
        unpack2(sc[3], s[6], s[7]);

        // ---- register online softmax (warp butterflies) ----
        float p[RPW], alpha[RPW];
        #pragma unroll
        for (int r = 0; r < RPW; r++) {
            float mx = s[r];
            #pragma unroll
            for (int o = 16; o; o >>= 1)
                mx = fmaxf(mx, __shfl_xor_sync(0xffffffffu, mx, o));
            float mn = fmaxf(m[r], mx);
            alpha[r] = __expf(m[r] - mn);
            m[r] = mn;
            float pv = __expf(s[r] - mn);
            p[r] = pv;
            float sm = pv;
            #pragma unroll
            for (int o = 16; o; o >>= 1)
                sm += __shfl_xor_sync(0xffffffffu, sm, o);
            l[r] = l[r] * alpha[r] + sm;
        }

        // ---- rescale accumulators ----
        #pragma unroll
        for (int r = 0; r < RPW; r++) {
            unsigned long long aa = pack2(alpha[r], alpha[r]);
            #pragma unroll
            for (int j = 0; j < 4; j++) mul2(acc[r][j], aa);
        }

        // ---- P*V: p broadcast via shuffle, V from row-major sK ----
        #pragma unroll 4
        for (int s2 = 0; s2 < CHUNK; s2++) {
            const ulonglong2 v0 = *(const ulonglong2*)&sK[s2 * KSTRIDE + lane * 4];
            const ulonglong2 v1 = *(const ulonglong2*)&sK[s2 * KSTRIDE + 128 + lane * 4];
            #pragma unroll
            for (int r = 0; r < RPW; r++) {
                float pr = __shfl_sync(0xffffffffu, p[r], s2);
                unsigned long long pp = pack2(pr, pr);
                fma2(acc[r][0], pp, v0.x);
                fma2(acc[r][1], pp, v0.y);
                fma2(acc[r][2], pp, v1.x);
                fma2(acc[r][3], pp, v1.y);
            }
        }
    }

    // ---- epilogue ----
    #pragma unroll
    for (int r = 0; r < RPW; r++) {
        int qg = qtile * ROWS + warp * RPW + r;
        if (qg >= NQ) continue;
        float inv = 1.0f / l[r];
        float r0, r1, r2, r3, r4, r5, r6, r7;
        unpack2(acc[r][0], r0, r1);
        unpack2(acc[r][1], r2, r3);
        unpack2(acc[r][2], r4, r5);
        unpack2(acc[r][3], r6, r7);
        float4 o0 = make_float4(r0 * inv, r1 * inv, r2 * inv, r3 * inv);
        float4 o1 = make_float4(r4 * inv, r5 * inv, r6 * inv, r7 * inv);
        size_t base = ((size_t)region * NQ + qg) * CC;
        *(float4*)&out[base + lane * 4]       = o0;
        *(float4*)&out[base + 128 + lane * 4] = o1;
    }
}

// ---------------- positions (second tuple output) ----------------
__global__ void pos_kernel(float* __restrict__ out, int out_size) {
    int t = threadIdx.x;
    if (t < NREG && out_size >= OUT_ELEMS + POS_ELEMS) {
        out[OUT_ELEMS + 2 * t + 0] = (float)(t / GDIM) * (1.0f / 7.0f);
        out[OUT_ELEMS + 2 * t + 1] = (float)(t % GDIM) * (1.0f / 7.0f);
    }
}

extern "C" void kernel_launch(void* const* d_in, const int* in_sizes, int n_in,
                              void* d_out, int out_size) {
    const float* images  = (const float*)d_in[0];
    const float* queries = (const float*)d_in[1];
    if (n_in >= 2 && in_sizes[0] == NQ * CC) {
        const float* t = images; images = queries; queries = t;
    }
    float* out = (float*)d_out;

    cudaFuncSetAttribute(attn_kernel,
                         cudaFuncAttributeMaxDynamicSharedMemorySize, SMEM_BYTES);

    // pos_kernel FIRST so ncu's "-s 5 -c 1" lands on attn_kernel (launch #6)
    pos_kernel<<<1, 64>>>(out, out_size);
    attn_kernel<<<196 * 2, THREADS, SMEM_BYTES>>>(images, queries, out);
}

// round 3
// speedup vs baseline: 1.6826x; 1.3933x over previous
#include <cuda_runtime.h>
#include <cstdint>

#define NB      4
#define GDIM    7
#define NREG    49
#define HH      224
#define CC      256
#define NQ      100
#define ROWS    64      // q rows per CTA (2 q-tiles)
#define THREADS 256     // 8 warps x 8 q-rows
#define KEYS    64      // keys per pass (two 32-key row strips)
#define NPASS   16
#define HSTRIDE (HH*CC) // image pixel-row stride in floats

#define KSTRIDE  260    // sK [KEYS][KSTRIDE]; 260 = 4*65 -> conflict-free lane-strided LDS.128
#define QTSTRIDE 68     // sQt [CC][QTSTRIDE] transposed queries (broadcast reads)
#define PSTRIDE  12     // sP floats per key (48B -> 3k mod 8 bank groups, conflict-free .128)

#define SK_FLOATS  (KEYS*KSTRIDE)        // 16640
#define SQT_FLOATS (CC*QTSTRIDE)         // 17408
#define SP_FLOATS  (8*KEYS*PSTRIDE)      // 6144
#define SMEM_FLOATS (2*SK_FLOATS + SQT_FLOATS + SP_FLOATS)
#define SMEM_BYTES  (SMEM_FLOATS*4)      // 227,328 B

#define OUT_ELEMS (NB*NREG*NQ*CC)
#define POS_ELEMS (NREG*2)

typedef unsigned long long u64;

// ---------------- packed f32x2 helpers ----------------
__device__ __forceinline__ u64 pack2(float a, float b) {
    u64 r; asm("mov.b64 %0, {%1, %2};" : "=l"(r) : "f"(a), "f"(b)); return r;
}
__device__ __forceinline__ void unpack2(u64 v, float& a, float& b) {
    asm("mov.b64 {%0, %1}, %2;" : "=f"(a), "=f"(b) : "l"(v));
}
__device__ __forceinline__ void fma2(u64& d, u64 a, u64 b) {
    asm("fma.rn.f32x2 %0, %1, %2, %0;" : "+l"(d) : "l"(a), "l"(b));
}
__device__ __forceinline__ void mul2(u64& d, u64 a) {
    asm("mul.rn.f32x2 %0, %1, %0;" : "+l"(d) : "l"(a));
}
__device__ __forceinline__ void add2(u64& d, u64 a) {
    asm("add.rn.f32x2 %0, %1, %0;" : "+l"(d) : "l"(a));
}

// ---------------- cp.async helpers ----------------
__device__ __forceinline__ uint32_t s2u(const void* p) {
    return (uint32_t)__cvta_generic_to_shared(p);
}
__device__ __forceinline__ void cp16(uint32_t s, const void* g) {
    asm volatile("cp.async.cg.shared.global [%0], [%1], 16;" :: "r"(s), "l"(g));
}
#define CP_COMMIT() asm volatile("cp.async.commit_group;")
#define CP_WAIT1()  asm volatile("cp.async.wait_group 1;")

// ---------------- fused attention ----------------
// grid: 392 CTAs (196 regions x 2 q-tiles), 256 threads
__global__ void __launch_bounds__(THREADS, 1)
attn_kernel(const float* __restrict__ images,
            const float* __restrict__ queries,
            float* __restrict__ out)
{
    extern __shared__ float smem[];
    float* sK0 = smem;
    float* sK1 = smem + SK_FLOATS;
    float* sQt = smem + 2*SK_FLOATS;
    float* sP  = sQt + SQT_FLOATS;

    const int bx     = blockIdx.x;
    const int region = bx >> 1;
    const int qtile  = bx & 1;
    const int b  = region / NREG;
    const int n  = region % NREG;
    const int gi = n / GDIM;
    const int gj = n % GDIM;

    const int tid  = threadIdx.x;
    const int lane = tid & 31;
    const int warp = tid >> 5;

    const float* imgbase = images + ((size_t)(b*HH + gi*32)*HH + gj*32)*CC;

    // thread-fixed copy geometry: c4 = float col, r0 = base key row
    const int cpc = (tid & 63) * 4;
    const int r0  = tid >> 6;            // 0..3
    const uint32_t sku0 = s2u(sK0);
    const uint32_t sku1 = s2u(sK1);

    // prefetch passes 0 and 1 (16 x 16B per thread each)
    #pragma unroll
    for (int k = 0; k < 16; k++) {
        int r = r0 + 4*k;
        cp16(sku0 + (r*KSTRIDE + cpc)*4,
             imgbase + (size_t)(r >> 5)*HSTRIDE + (r & 31)*CC + cpc);
    }
    CP_COMMIT();
    #pragma unroll
    for (int k = 0; k < 16; k++) {
        int r = r0 + 4*k;
        cp16(sku1 + (r*KSTRIDE + cpc)*4,
             imgbase + (size_t)(2 + (r >> 5))*HSTRIDE + (r & 31)*CC + cpc);
    }
    CP_COMMIT();

    // stage Q transposed: sQt[c][q]  (one-time; conflicts amortized)
    for (int id = tid; id < ROWS*CC; id += THREADS) {
        int q = id >> 8;
        int c = id & 255;
        int qg = qtile*ROWS + q;
        sQt[c*QTSTRIDE + q] = (qg < NQ) ? queries[qg*CC + c] : 0.0f;
    }

    float m[8];
    u64 acc2[4][8];     // acc2[rp][j] = (out[2rp], out[2rp+1]) at channel j
    u64 accl[4];        // row-sum pairs (softmax denominators)
    #pragma unroll
    for (int r = 0; r < 8; r++) m[r] = -1e30f;
    #pragma unroll
    for (int rp = 0; rp < 4; rp++) {
        accl[rp] = 0ull;
        #pragma unroll
        for (int j = 0; j < 8; j++) acc2[rp][j] = 0ull;
    }

    float* sPw = sP + warp*(KEYS*PSTRIDE);
    const float* qb = sQt + warp*8;

    for (int p = 0; p < NPASS; p++) {
        CP_WAIT1();
        __syncthreads();
        const float* sK = (p & 1) ? sK1 : sK0;

        // ---- scores: 8 rows x 64 keys (lane holds keys lane, lane+32) ----
        u64 sa01=0, sa23=0, sa45=0, sa67=0;
        u64 sb01=0, sb23=0, sb45=0, sb67=0;
        const float* kA = sK + lane*KSTRIDE;
        const float* kB = sK + (lane+32)*KSTRIDE;
        #pragma unroll 4
        for (int cb = 0; cb < 64; cb++) {
            float4 ka = *(const float4*)(kA + cb*4);
            float4 kb = *(const float4*)(kB + cb*4);
            #pragma unroll
            for (int cc = 0; cc < 4; cc++) {
                const float* qp = qb + (cb*4 + cc)*QTSTRIDE;
                ulonglong2 q03 = *(const ulonglong2*)qp;        // rows (0,1),(2,3)
                ulonglong2 q47 = *(const ulonglong2*)(qp + 4);  // rows (4,5),(6,7)
                float kaf = cc==0 ? ka.x : cc==1 ? ka.y : cc==2 ? ka.z : ka.w;
                float kbf = cc==0 ? kb.x : cc==1 ? kb.y : cc==2 ? kb.z : kb.w;
                u64 kka = pack2(kaf, kaf);
                u64 kkb = pack2(kbf, kbf);
                fma2(sa01, q03.x, kka); fma2(sa23, q03.y, kka);
                fma2(sa45, q47.x, kka); fma2(sa67, q47.y, kka);
                fma2(sb01, q03.x, kkb); fma2(sb23, q03.y, kkb);
                fma2(sb45, q47.x, kkb); fma2(sb67, q47.y, kkb);
            }
        }
        float sa[8], sb[8];
        unpack2(sa01, sa[0], sa[1]); unpack2(sa23, sa[2], sa[3]);
        unpack2(sa45, sa[4], sa[5]); unpack2(sa67, sa[6], sa[7]);
        unpack2(sb01, sb[0], sb[1]); unpack2(sb23, sb[2], sb[3]);
        unpack2(sb45, sb[4], sb[5]); unpack2(sb67, sb[6], sb[7]);

        // ---- online softmax (max via butterfly; sum folded into PV) ----
        float pa[8], pb[8], al[8];
        #pragma unroll
        for (int r = 0; r < 8; r++) {
            float mx = fmaxf(sa[r], sb[r]);
            #pragma unroll
            for (int o = 16; o; o >>= 1)
                mx = fmaxf(mx, __shfl_xor_sync(0xffffffffu, mx, o));
            float mn = fmaxf(m[r], mx);
            al[r] = __expf(m[r] - mn);
            m[r]  = mn;
            pa[r] = __expf(sa[r] - mn);
            pb[r] = __expf(sb[r] - mn);
        }
        #pragma unroll
        for (int rp = 0; rp < 4; rp++) {
            u64 aa = pack2(al[2*rp], al[2*rp+1]);
            #pragma unroll
            for (int j = 0; j < 8; j++) mul2(acc2[rp][j], aa);
            mul2(accl[rp], aa);
        }

        // ---- publish p to per-warp sP (conflict-free .128) ----
        *(float4*)&sPw[lane*PSTRIDE]          = make_float4(pa[0],pa[1],pa[2],pa[3]);
        *(float4*)&sPw[lane*PSTRIDE + 4]      = make_float4(pa[4],pa[5],pa[6],pa[7]);
        *(float4*)&sPw[(lane+32)*PSTRIDE]     = make_float4(pb[0],pb[1],pb[2],pb[3]);
        *(float4*)&sPw[(lane+32)*PSTRIDE + 4] = make_float4(pb[4],pb[5],pb[6],pb[7]);
        __syncwarp();

        // ---- P*V (+ fold row-sums into accl) ----
        #pragma unroll 2
        for (int s2 = 0; s2 < KEYS; s2++) {
            ulonglong2 p03 = *(const ulonglong2*)&sPw[s2*PSTRIDE];      // (p0,p1),(p2,p3)
            ulonglong2 p47 = *(const ulonglong2*)&sPw[s2*PSTRIDE + 4];  // (p4,p5),(p6,p7)
            float4 v0 = *(const float4*)(sK + s2*KSTRIDE + lane*4);
            float4 v1 = *(const float4*)(sK + s2*KSTRIDE + 128 + lane*4);
            float vf[8] = {v0.x, v0.y, v0.z, v0.w, v1.x, v1.y, v1.z, v1.w};
            #pragma unroll
            for (int j = 0; j < 8; j++) {
                u64 vd = pack2(vf[j], vf[j]);
                fma2(acc2[0][j], p03.x, vd);
                fma2(acc2[1][j], p03.y, vd);
                fma2(acc2[2][j], p47.x, vd);
                fma2(acc2[3][j], p47.y, vd);
            }
            add2(accl[0], p03.x); add2(accl[1], p03.y);
            add2(accl[2], p47.x); add2(accl[3], p47.y);
        }

        __syncthreads();   // all warps done reading sK[p&1]

        // prefetch pass p+2 into the buffer just freed
        if (p + 2 < NPASS) {
            uint32_t sb_ = (p & 1) ? sku1 : sku0;
            const float* gp = imgbase + (size_t)(2*(p+2))*HSTRIDE;
            #pragma unroll
            for (int k = 0; k < 16; k++) {
                int r = r0 + 4*k;
                cp16(sb_ + (r*KSTRIDE + cpc)*4,
                     gp + (size_t)(r >> 5)*HSTRIDE + (r & 31)*CC + cpc);
            }
        }
        CP_COMMIT();
    }

    // ---- epilogue: normalize and store ----
    #pragma unroll
    for (int rp = 0; rp < 4; rp++) {
        float l0, l1;
        unpack2(accl[rp], l0, l1);
        float lo[8], hi[8];
        #pragma unroll
        for (int j = 0; j < 8; j++) unpack2(acc2[rp][j], lo[j], hi[j]);
        int q0 = qtile*ROWS + warp*8 + 2*rp;
        if (q0 < NQ) {
            float inv = 1.0f / l0;
            size_t base = ((size_t)region*NQ + q0)*CC;
            *(float4*)&out[base + lane*4] =
                make_float4(lo[0]*inv, lo[1]*inv, lo[2]*inv, lo[3]*inv);
            *(float4*)&out[base + 128 + lane*4] =
                make_float4(lo[4]*inv, lo[5]*inv, lo[6]*inv, lo[7]*inv);
        }
        if (q0 + 1 < NQ) {
            float inv = 1.0f / l1;
            size_t base = ((size_t)region*NQ + q0 + 1)*CC;
            *(float4*)&out[base + lane*4] =
                make_float4(hi[0]*inv, hi[1]*inv, hi[2]*inv, hi[3]*inv);
            *(float4*)&out[base + 128 + lane*4] =
                make_float4(hi[4]*inv, hi[5]*inv, hi[6]*inv, hi[7]*inv);
        }
    }
}

// ---------------- positions (second tuple output) ----------------
__global__ void pos_kernel(float* __restrict__ out, int out_size) {
    int t = threadIdx.x;
    if (t < NREG && out_size >= OUT_ELEMS + POS_ELEMS) {
        out[OUT_ELEMS + 2*t + 0] = (float)(t / GDIM) * (1.0f / 7.0f);
        out[OUT_ELEMS + 2*t + 1] = (float)(t % GDIM) * (1.0f / 7.0f);
    }
}

extern "C" void kernel_launch(void* const* d_in, const int* in_sizes, int n_in,
                              void* d_out, int out_size) {
    const float* images  = (const float*)d_in[0];
    const float* queries = (const float*)d_in[1];
    if (n_in >= 2 && in_sizes[0] == NQ*CC) {
        const float* t = images; images = queries; queries = t;
    }
    float* out = (float*)d_out;

    cudaFuncSetAttribute(attn_kernel,
                         cudaFuncAttributeMaxDynamicSharedMemorySize, SMEM_BYTES);

    // pos_kernel first so ncu "-s 5 -c 1" lands on attn_kernel
    pos_kernel<<<1, 64>>>(out, out_size);
    attn_kernel<<<196*2, THREADS, SMEM_BYTES>>>(images, queries, out);
}

// round 4
// speedup vs baseline: 1.6842x; 1.0009x over previous
#include <cuda_runtime.h>
#include <cstdint>

#define NB      4
#define GDIM    7
#define NREG    49
#define HH      224
#define CC      256
#define NQ      100
#define ROWS    64      // q rows per CTA (2 q-tiles)
#define THREADS 256     // 8 warps x 8 q-rows
#define KEYS    64      // keys per pass (two 32-key row strips)
#define NPASS   16
#define HSTRIDE (HH*CC) // image pixel-row stride in floats

#define KSTRIDE  260    // sK [KEYS][KSTRIDE]; 260 = 4*65 -> conflict-free lane-strided LDS.128
#define QTSTRIDE 68     // sQt [CC][QTSTRIDE] transposed queries (broadcast reads)
#define PSTRIDE  12     // sP floats per key (48B -> 3k mod 8 bank groups, conflict-free .128)

#define SK_FLOATS  (KEYS*KSTRIDE)        // 16640
#define SQT_FLOATS (CC*QTSTRIDE)         // 17408
#define SP_FLOATS  (8*KEYS*PSTRIDE)      // 6144
#define SMEM_FLOATS (2*SK_FLOATS + SQT_FLOATS + SP_FLOATS)
#define SMEM_BYTES  (SMEM_FLOATS*4)      // 227,328 B

#define OUT_ELEMS (NB*NREG*NQ*CC)
#define POS_ELEMS (NREG*2)

typedef unsigned long long u64;

// ---------------- packed f32x2 helpers ----------------
__device__ __forceinline__ u64 pack2(float a, float b) {
    u64 r; asm("mov.b64 %0, {%1, %2};" : "=l"(r) : "f"(a), "f"(b)); return r;
}
__device__ __forceinline__ void unpack2(u64 v, float& a, float& b) {
    asm("mov.b64 {%0, %1}, %2;" : "=f"(a), "=f"(b) : "l"(v));
}
__device__ __forceinline__ void fma2(u64& d, u64 a, u64 b) {
    asm("fma.rn.f32x2 %0, %1, %2, %0;" : "+l"(d) : "l"(a), "l"(b));
}
__device__ __forceinline__ void mul2(u64& d, u64 a) {
    asm("mul.rn.f32x2 %0, %1, %0;" : "+l"(d) : "l"(a));
}
__device__ __forceinline__ void add2(u64& d, u64 a) {
    asm("add.rn.f32x2 %0, %1, %0;" : "+l"(d) : "l"(a));
}

// ---------------- cp.async helpers ----------------
__device__ __forceinline__ uint32_t s2u(const void* p) {
    return (uint32_t)__cvta_generic_to_shared(p);
}
__device__ __forceinline__ void cp16(uint32_t s, const void* g) {
    asm volatile("cp.async.cg.shared.global [%0], [%1], 16;" :: "r"(s), "l"(g));
}
#define CP_COMMIT() asm volatile("cp.async.commit_group;")
#define CP_WAIT1()  asm volatile("cp.async.wait_group 1;")

// ---------------- fused attention ----------------
// grid: 392 CTAs (196 regions x 2 q-tiles), 256 threads
__global__ void __launch_bounds__(THREADS, 1)
attn_kernel(const float* __restrict__ images,
            const float* __restrict__ queries,
            float* __restrict__ out)
{
    extern __shared__ float smem[];
    float* sK0 = smem;
    float* sK1 = smem + SK_FLOATS;
    float* sQt = smem + 2*SK_FLOATS;
    float* sP  = sQt + SQT_FLOATS;

    const int bx     = blockIdx.x;
    const int region = bx >> 1;
    const int qtile  = bx & 1;
    const int b  = region / NREG;
    const int n  = region % NREG;
    const int gi = n / GDIM;
    const int gj = n % GDIM;

    const int tid  = threadIdx.x;
    const int lane = tid & 31;
    const int warp = tid >> 5;

    const float* imgbase = images + ((size_t)(b*HH + gi*32)*HH + gj*32)*CC;

    // thread-fixed copy geometry: c4 = float col, r0 = base key row
    const int cpc = (tid & 63) * 4;
    const int r0  = tid >> 6;            // 0..3
    const uint32_t sku0 = s2u(sK0);
    const uint32_t sku1 = s2u(sK1);

    // prefetch passes 0 and 1 (16 x 16B per thread each)
    #pragma unroll
    for (int k = 0; k < 16; k++) {
        int r = r0 + 4*k;
        cp16(sku0 + (r*KSTRIDE + cpc)*4,
             imgbase + (size_t)(r >> 5)*HSTRIDE + (r & 31)*CC + cpc);
    }
    CP_COMMIT();
    #pragma unroll
    for (int k = 0; k < 16; k++) {
        int r = r0 + 4*k;
        cp16(sku1 + (r*KSTRIDE + cpc)*4,
             imgbase + (size_t)(2 + (r >> 5))*HSTRIDE + (r & 31)*CC + cpc);
    }
    CP_COMMIT();

    // stage Q transposed: sQt[c][q]  (one-time; conflicts amortized)
    for (int id = tid; id < ROWS*CC; id += THREADS) {
        int q = id >> 8;
        int c = id & 255;
        int qg = qtile*ROWS + q;
        sQt[c*QTSTRIDE + q] = (qg < NQ) ? queries[qg*CC + c] : 0.0f;
    }

    float m[8];
    u64 acc2[4][8];     // acc2[rp][j] = (out[2rp], out[2rp+1]) at channel j
    u64 accl[4];        // row-sum pairs (softmax denominators)
    #pragma unroll
    for (int r = 0; r < 8; r++) m[r] = -1e30f;
    #pragma unroll
    for (int rp = 0; rp < 4; rp++) {
        accl[rp] = 0ull;
        #pragma unroll
        for (int j = 0; j < 8; j++) acc2[rp][j] = 0ull;
    }

    float* sPw = sP + warp*(KEYS*PSTRIDE);
    const float* qb = sQt + warp*8;

    for (int p = 0; p < NPASS; p++) {
        CP_WAIT1();
        __syncthreads();
        const float* sK = (p & 1) ? sK1 : sK0;

        // ---- scores: 8 rows x 64 keys (lane holds keys lane, lane+32) ----
        u64 sa01=0, sa23=0, sa45=0, sa67=0;
        u64 sb01=0, sb23=0, sb45=0, sb67=0;
        const float* kA = sK + lane*KSTRIDE;
        const float* kB = sK + (lane+32)*KSTRIDE;
        #pragma unroll 4
        for (int cb = 0; cb < 64; cb++) {
            float4 ka = *(const float4*)(kA + cb*4);
            float4 kb = *(const float4*)(kB + cb*4);
            #pragma unroll
            for (int cc = 0; cc < 4; cc++) {
                const float* qp = qb + (cb*4 + cc)*QTSTRIDE;
                ulonglong2 q03 = *(const ulonglong2*)qp;        // rows (0,1),(2,3)
                ulonglong2 q47 = *(const ulonglong2*)(qp + 4);  // rows (4,5),(6,7)
                float kaf = cc==0 ? ka.x : cc==1 ? ka.y : cc==2 ? ka.z : ka.w;
                float kbf = cc==0 ? kb.x : cc==1 ? kb.y : cc==2 ? kb.z : kb.w;
                u64 kka = pack2(kaf, kaf);
                u64 kkb = pack2(kbf, kbf);
                fma2(sa01, q03.x, kka); fma2(sa23, q03.y, kka);
                fma2(sa45, q47.x, kka); fma2(sa67, q47.y, kka);
                fma2(sb01, q03.x, kkb); fma2(sb23, q03.y, kkb);
                fma2(sb45, q47.x, kkb); fma2(sb67, q47.y, kkb);
            }
        }
        float sa[8], sb[8];
        unpack2(sa01, sa[0], sa[1]); unpack2(sa23, sa[2], sa[3]);
        unpack2(sa45, sa[4], sa[5]); unpack2(sa67, sa[6], sa[7]);
        unpack2(sb01, sb[0], sb[1]); unpack2(sb23, sb[2], sb[3]);
        unpack2(sb45, sb[4], sb[5]); unpack2(sb67, sb[6], sb[7]);

        // ---- online softmax (max via butterfly; sum folded into PV) ----
        float pa[8], pb[8], al[8];
        #pragma unroll
        for (int r = 0; r < 8; r++) {
            float mx = fmaxf(sa[r], sb[r]);
            #pragma unroll
            for (int o = 16; o; o >>= 1)
                mx = fmaxf(mx, __shfl_xor_sync(0xffffffffu, mx, o));
            float mn = fmaxf(m[r], mx);
            al[r] = __expf(m[r] - mn);
            m[r]  = mn;
            pa[r] = __expf(sa[r] - mn);
            pb[r] = __expf(sb[r] - mn);
        }
        #pragma unroll
        for (int rp = 0; rp < 4; rp++) {
            u64 aa = pack2(al[2*rp], al[2*rp+1]);
            #pragma unroll
            for (int j = 0; j < 8; j++) mul2(acc2[rp][j], aa);
            mul2(accl[rp], aa);
        }

        // ---- publish p to per-warp sP (conflict-free .128) ----
        *(float4*)&sPw[lane*PSTRIDE]          = make_float4(pa[0],pa[1],pa[2],pa[3]);
        *(float4*)&sPw[lane*PSTRIDE + 4]      = make_float4(pa[4],pa[5],pa[6],pa[7]);
        *(float4*)&sPw[(lane+32)*PSTRIDE]     = make_float4(pb[0],pb[1],pb[2],pb[3]);
        *(float4*)&sPw[(lane+32)*PSTRIDE + 4] = make_float4(pb[4],pb[5],pb[6],pb[7]);
        __syncwarp();

        // ---- P*V (+ fold row-sums into accl) ----
        #pragma unroll 2
        for (int s2 = 0; s2 < KEYS; s2++) {
            ulonglong2 p03 = *(const ulonglong2*)&sPw[s2*PSTRIDE];      // (p0,p1),(p2,p3)
            ulonglong2 p47 = *(const ulonglong2*)&sPw[s2*PSTRIDE + 4];  // (p4,p5),(p6,p7)
            float4 v0 = *(const float4*)(sK + s2*KSTRIDE + lane*4);
            float4 v1 = *(const float4*)(sK + s2*KSTRIDE + 128 + lane*4);
            float vf[8] = {v0.x, v0.y, v0.z, v0.w, v1.x, v1.y, v1.z, v1.w};
            #pragma unroll
            for (int j = 0; j < 8; j++) {
                u64 vd = pack2(vf[j], vf[j]);
                fma2(acc2[0][j], p03.x, vd);
                fma2(acc2[1][j], p03.y, vd);
                fma2(acc2[2][j], p47.x, vd);
                fma2(acc2[3][j], p47.y, vd);
            }
            add2(accl[0], p03.x); add2(accl[1], p03.y);
            add2(accl[2], p47.x); add2(accl[3], p47.y);
        }

        __syncthreads();   // all warps done reading sK[p&1]

        // prefetch pass p+2 into the buffer just freed
        if (p + 2 < NPASS) {
            uint32_t sb_ = (p & 1) ? sku1 : sku0;
            const float* gp = imgbase + (size_t)(2*(p+2))*HSTRIDE;
            #pragma unroll
            for (int k = 0; k < 16; k++) {
                int r = r0 + 4*k;
                cp16(sb_ + (r*KSTRIDE + cpc)*4,
                     gp + (size_t)(r >> 5)*HSTRIDE + (r & 31)*CC + cpc);
            }
        }
        CP_COMMIT();
    }

    // ---- epilogue: normalize and store ----
    #pragma unroll
    for (int rp = 0; rp < 4; rp++) {
        float l0, l1;
        unpack2(accl[rp], l0, l1);
        float lo[8], hi[8];
        #pragma unroll
        for (int j = 0; j < 8; j++) unpack2(acc2[rp][j], lo[j], hi[j]);
        int q0 = qtile*ROWS + warp*8 + 2*rp;
        if (q0 < NQ) {
            float inv = 1.0f / l0;
            size_t base = ((size_t)region*NQ + q0)*CC;
            *(float4*)&out[base + lane*4] =
                make_float4(lo[0]*inv, lo[1]*inv, lo[2]*inv, lo[3]*inv);
            *(float4*)&out[base + 128 + lane*4] =
                make_float4(lo[4]*inv, lo[5]*inv, lo[6]*inv, lo[7]*inv);
        }
        if (q0 + 1 < NQ) {
            float inv = 1.0f / l1;
            size_t base = ((size_t)region*NQ + q0 + 1)*CC;
            *(float4*)&out[base + lane*4] =
                make_float4(hi[0]*inv, hi[1]*inv, hi[2]*inv, hi[3]*inv);
            *(float4*)&out[base + 128 + lane*4] =
                make_float4(hi[4]*inv, hi[5]*inv, hi[6]*inv, hi[7]*inv);
        }
    }
}

// ---------------- positions (second tuple output) ----------------
__global__ void pos_kernel(float* __restrict__ out, int out_size) {
    int t = threadIdx.x;
    if (t < NREG && out_size >= OUT_ELEMS + POS_ELEMS) {
        out[OUT_ELEMS + 2*t + 0] = (float)(t / GDIM) * (1.0f / 7.0f);
        out[OUT_ELEMS + 2*t + 1] = (float)(t % GDIM) * (1.0f / 7.0f);
    }
}

extern "C" void kernel_launch(void* const* d_in, const int* in_sizes, int n_in,
                              void* d_out, int out_size) {
    const float* images  = (const float*)d_in[0];
    const float* queries = (const float*)d_in[1];
    if (n_in >= 2 && in_sizes[0] == NQ*CC) {
        const float* t = images; images = queries; queries = t;
    }
    float* out = (float*)d_out;

    cudaFuncSetAttribute(attn_kernel,
                         cudaFuncAttributeMaxDynamicSharedMemorySize, SMEM_BYTES);

    // pos_kernel first so ncu "-s 5 -c 1" lands on attn_kernel
    pos_kernel<<<1, 64>>>(out, out_size);
    attn_kernel<<<196*2, THREADS, SMEM_BYTES>>>(images, queries, out);
}